// round 6
// baseline (speedup 1.0000x reference)
#include <cuda_runtime.h>
#include <math.h>

#define HH    512
#define NIMG  72          // B(8) * M(3) * W(3); wavelength = img % 3
#define NWL   3
#define NLAY  5
#define CSTR  514         // staging tile column stride in float2 (bank-offset 4 words)
#define TWO_PI 6.2831853071795864769f
#define PI_F   3.14159265358979323846f

// -------- precomputed tables (__device__ globals = sanctioned scratch) --------
// H tables are stored PERMUTED on both axes: Hp[w][c][p] = H(sig(c), sig(p)) * scale,
// where sig(p) = 16*brev5(p&31) + (p>>5) is the storage->spectral map of the warp FFT.
__device__ float2 d_HL[NWL * HH * HH];
__device__ float2 d_HD[NWL * HH * HH];
__device__ float2 d_expP[NLAY * NWL * HH * HH];      // natural order (layers>0 scaled 1/512)

__device__ __forceinline__ float2 cmulf(float2 a, float2 b) {
    return make_float2(a.x * b.x - a.y * b.y, a.x * b.y + a.y * b.x);
}
template <int SGN>
__device__ __forceinline__ float2 muli(float2 z) {   // SGN * i * z
    return (SGN > 0) ? make_float2(-z.y, z.x) : make_float2(z.y, -z.x);
}
__device__ __forceinline__ float2 shflx(float2 z, int m) {
    return make_float2(__shfl_xor_sync(0xffffffffu, z.x, m),
                       __shfl_xor_sync(0xffffffffu, z.y, m));
}

// natural-order 8-point DFT
template <int SGN>
__device__ __forceinline__ void dft8(float2 v[8]) {
    const float C = 0.70710678118654752f;
    const float sg = (float)SGN;
    float2 t0 = make_float2(v[0].x + v[4].x, v[0].y + v[4].y);
    float2 t1 = make_float2(v[0].x - v[4].x, v[0].y - v[4].y);
    float2 t2 = make_float2(v[2].x + v[6].x, v[2].y + v[6].y);
    float2 t3 = make_float2(v[2].x - v[6].x, v[2].y - v[6].y);
    float2 u0 = make_float2(v[1].x + v[5].x, v[1].y + v[5].y);
    float2 u1 = make_float2(v[1].x - v[5].x, v[1].y - v[5].y);
    float2 u2 = make_float2(v[3].x + v[7].x, v[3].y + v[7].y);
    float2 u3 = make_float2(v[3].x - v[7].x, v[3].y - v[7].y);
    float2 it3 = muli<SGN>(t3);
    float2 iu3 = muli<SGN>(u3);
    float2 E0 = make_float2(t0.x + t2.x, t0.y + t2.y);
    float2 E2 = make_float2(t0.x - t2.x, t0.y - t2.y);
    float2 E1 = make_float2(t1.x + it3.x, t1.y + it3.y);
    float2 E3 = make_float2(t1.x - it3.x, t1.y - it3.y);
    float2 O0 = make_float2(u0.x + u2.x, u0.y + u2.y);
    float2 O2 = make_float2(u0.x - u2.x, u0.y - u2.y);
    float2 O1 = make_float2(u1.x + iu3.x, u1.y + iu3.y);
    float2 O3 = make_float2(u1.x - iu3.x, u1.y - iu3.y);
    float2 w1o = make_float2(C * (O1.x - sg * O1.y), C * (O1.y + sg * O1.x));
    float2 w2o = muli<SGN>(O2);
    float2 w3o = make_float2(-C * (O3.x + sg * O3.y), C * (sg * O3.x - O3.y));
    v[0] = make_float2(E0.x + O0.x, E0.y + O0.y);
    v[4] = make_float2(E0.x - O0.x, E0.y - O0.y);
    v[1] = make_float2(E1.x + w1o.x, E1.y + w1o.y);
    v[5] = make_float2(E1.x - w1o.x, E1.y - w1o.y);
    v[2] = make_float2(E2.x + w2o.x, E2.y + w2o.y);
    v[6] = make_float2(E2.x - w2o.x, E2.y - w2o.y);
    v[3] = make_float2(E3.x + w3o.x, E3.y + w3o.y);
    v[7] = make_float2(E3.x - w3o.x, E3.y - w3o.y);
}

// natural-order 16-point DFT in registers (two dft8 + combine)
template <int SGN>
__device__ __forceinline__ void dft16(float2 v[16]) {
    float2 e[8], o[8];
#pragma unroll
    for (int k = 0; k < 8; k++) { e[k] = v[2 * k]; o[k] = v[2 * k + 1]; }
    dft8<SGN>(e);
    dft8<SGN>(o);
    const float CC[8] = {1.0f, 0.92387953251128674f, 0.70710678118654752f,
                         0.38268343236508977f, 0.0f, -0.38268343236508977f,
                         -0.70710678118654752f, -0.92387953251128674f};
    const float SS[8] = {0.0f, 0.38268343236508977f, 0.70710678118654752f,
                         0.92387953251128674f, 1.0f, 0.92387953251128674f,
                         0.70710678118654752f, 0.38268343236508977f};
#pragma unroll
    for (int r = 0; r < 8; r++) {
        float2 w = make_float2(CC[r], (float)SGN * SS[r]);
        float2 t = cmulf(o[r], w);
        v[r]     = make_float2(e[r].x + t.x, e[r].y + t.y);
        v[r + 8] = make_float2(e[r].x - t.x, e[r].y - t.y);
    }
}

// DIF radix-2 cross-lane stage (forward): low: a+b ; high: (a-b)*W
template <int M>
__device__ __forceinline__ void difstage(float2 v[16], float2 W, int l) {
    bool hi = (l & M) != 0;
#pragma unroll
    for (int r = 0; r < 16; r++) {
        float2 p = shflx(v[r], M);
        float2 d = hi ? make_float2(p.x - v[r].x, p.y - v[r].y)
                      : make_float2(v[r].x + p.x, v[r].y + p.y);
        if (hi) d = cmulf(d, W);
        v[r] = d;
    }
}

// DIT radix-2 cross-lane stage (inverse): twiddle b first; low: a+Wb ; high: a-Wb
template <int M>
__device__ __forceinline__ void ditstage(float2 v[16], float2 W, int l) {
    bool hi = (l & M) != 0;
#pragma unroll
    for (int r = 0; r < 16; r++) {
        float2 z = v[r];
        if (hi) z = cmulf(z, W);
        float2 p = shflx(z, M);
        v[r] = hi ? make_float2(p.x - z.x, p.y - z.y)
                  : make_float2(z.x + p.x, z.y + p.y);
    }
}

// forward 512-pt warp FFT (SGN=-1):
// in: v[j] = x[32j + l] (natural)   out: v[r] = X[16*brev5(l) + r] (permuted)
__device__ __forceinline__ void wfft_fwd(float2 v[16], int l) {
    const int SGN = -1;
    dft16<SGN>(v);
    float s, c;
    __sincosf((float)SGN * TWO_PI * (float)l * (1.0f / 512.0f), &s, &c);
    float2 w = make_float2(c, s), tw = w;
    v[1] = cmulf(v[1], tw);
#pragma unroll
    for (int r = 2; r < 16; r++) { tw = cmulf(tw, w); v[r] = cmulf(v[r], tw); }
    float2 wA, wB, wC;
    __sincosf((float)SGN * PI_F * (float)(l & 15) * (1.0f / 16.0f), &s, &c); wA = make_float2(c, s);
    __sincosf((float)SGN * PI_F * (float)(l & 7)  * (1.0f / 8.0f),  &s, &c); wB = make_float2(c, s);
    __sincosf((float)SGN * PI_F * (float)(l & 3)  * (1.0f / 4.0f),  &s, &c); wC = make_float2(c, s);
    float2 wD = (l & 1) ? make_float2(0.0f, (float)SGN) : make_float2(1.0f, 0.0f);
    difstage<16>(v, wA, l);
    difstage<8>(v, wB, l);
    difstage<4>(v, wC, l);
    difstage<2>(v, wD, l);
    difstage<1>(v, make_float2(1.0f, 0.0f), l);
}

// inverse 512-pt warp FFT (SGN=+1, unnormalized):
// in: v[r] = Y[16*brev5(l) + r] (permuted)   out: v[j] = 512*x[32j + l] /512-folded elsewhere
__device__ __forceinline__ void wfft_inv(float2 v[16], int l) {
    const int SGN = +1;
    float s, c;
    float2 wA, wB, wC;
    __sincosf((float)SGN * PI_F * (float)(l & 3)  * (1.0f / 4.0f),  &s, &c); wC = make_float2(c, s);
    __sincosf((float)SGN * PI_F * (float)(l & 7)  * (1.0f / 8.0f),  &s, &c); wB = make_float2(c, s);
    __sincosf((float)SGN * PI_F * (float)(l & 15) * (1.0f / 16.0f), &s, &c); wA = make_float2(c, s);
    float2 wD = (l & 1) ? make_float2(0.0f, (float)SGN) : make_float2(1.0f, 0.0f);
    ditstage<1>(v, make_float2(1.0f, 0.0f), l);
    ditstage<2>(v, wD, l);
    ditstage<4>(v, wC, l);
    ditstage<8>(v, wB, l);
    ditstage<16>(v, wA, l);
    __sincosf((float)SGN * TWO_PI * (float)l * (1.0f / 512.0f), &s, &c);
    float2 w = make_float2(c, s), tw = w;
    v[1] = cmulf(v[1], tw);
#pragma unroll
    for (int r = 2; r < 16; r++) { tw = cmulf(tw, w); v[r] = cmulf(v[r], tw); }
    dft16<SGN>(v);
}

// ---------------- init kernels ----------------

__device__ __forceinline__ int sigmap(int p) {       // storage -> spectral index
    return 16 * (int)(__brev((unsigned)(p & 31)) >> 27) + (p >> 5);
}

__global__ void __launch_bounds__(256) k_initH() {
    int idx = blockIdx.x * 256 + threadIdx.x;
    if (idx >= NWL * HH * HH) return;
    int w = idx / (HH * HH);
    int cs = (idx >> 9) & 511;                // storage row (kx axis)
    int ps = idx & 511;                       // storage col (ky axis)
    int r = sigmap(cs);
    int c = sigmap(ps);
    const float wls[3] = {5.32e-07f, 6.33e-07f, 8.5e-07f};
    const float TW = TWO_PI;
    float mr = (float)((r < 256) ? r : r - 512);
    float mc = (float)((c < 256) ? c : c - 512);
    double invnd = 1.0 / (512.0 * 8e-06);
    float fr = (float)((double)mr * invnd);
    float fc = (float)((double)mc * invnd);
    float kx = __fmul_rn(TW, fr);
    float ky = __fmul_rn(TW, fc);
    float kk = __fdiv_rn(TW, wls[w]);
    float arg = __fsub_rn(__fsub_rn(__fmul_rn(kk, kk), __fmul_rn(kx, kx)),
                          __fmul_rn(ky, ky));
    const float SL = 1.0f / 512.0f;
    const float SD = 1.0f / 512.0f;           // 11 total 1/512 factors
    float2 hl, hd;
    if (arg >= 0.0f) {
        float kz = __fsqrt_rn(arg);
        float thL = __fmul_rn(kz, 0.03f);
        float thD = __fmul_rn(kz, 0.1f);
        double sl, cl, sd, cd;
        sincos((double)thL, &sl, &cl);
        sincos((double)thD, &sd, &cd);
        hl = make_float2((float)cl * SL, (float)sl * SL);
        hd = make_float2((float)cd * SD, (float)sd * SD);
    } else {
        float a = __fsqrt_rn(-arg);
        hl = make_float2(expf(-__fmul_rn(a, 0.03f)) * SL, 0.0f);
        hd = make_float2(expf(-__fmul_rn(a, 0.1f)) * SD, 0.0f);
    }
    d_HL[idx] = hl;
    d_HD[idx] = hd;
}

__global__ void __launch_bounds__(256) k_initP(const float* __restrict__ pm) {
    int idx = blockIdx.x * 256 + threadIdx.x;
    if (idx >= NLAY * NWL * HH * HH) return;
    float p = pm[idx];
    float s, c;
    __sincosf(p, &s, &c);
    int layer = idx / (NWL * HH * HH);
    float sc = (layer == 0) ? 1.0f : (1.0f / 512.0f);
    d_expP[idx] = make_float2(c * sc, s * sc);
}

// ---------------- row kernels: 1 warp = 1 row, 8 rows/block, no smem ----------------

__global__ void __launch_bounds__(256, 2) k_first(const float* __restrict__ xr,
                                                  const float* __restrict__ xi,
                                                  float2* __restrict__ f) {
    int l = threadIdx.x & 31;
    int line = blockIdx.x * 8 + (threadIdx.x >> 5);
    int img = line >> 9, y = line & 511, w = img % 3;
    const float2* P = d_expP + ((size_t)w * HH + y) * HH;  // layer 0, natural order
    size_t base = (size_t)line * HH;
    float2 v[16];
#pragma unroll
    for (int j = 0; j < 16; j++) {
        int x = 32 * j + l;
        float2 a = make_float2(xr[base + x], xi[base + x]);
        v[j] = cmulf(a, P[x]);
    }
    wfft_fwd(v, l);
#pragma unroll
    for (int r = 0; r < 16; r++) f[base + 32 * r + l] = v[r];
}

__global__ void __launch_bounds__(256, 2) k_rowmid(float2* __restrict__ f, int layer) {
    int l = threadIdx.x & 31;
    int line = blockIdx.x * 8 + (threadIdx.x >> 5);
    int img = line >> 9, y = line & 511, w = img % 3;
    const float2* P = d_expP + (((size_t)layer * NWL + w) * HH + y) * HH;
    size_t base = (size_t)line * HH;
    float2 v[16];
#pragma unroll
    for (int r = 0; r < 16; r++) v[r] = f[base + 32 * r + l];
    wfft_inv(v, l);
#pragma unroll
    for (int j = 0; j < 16; j++) v[j] = cmulf(v[j], P[32 * j + l]);
    wfft_fwd(v, l);
#pragma unroll
    for (int r = 0; r < 16; r++) f[base + 32 * r + l] = v[r];
}

__global__ void __launch_bounds__(256, 2) k_last(float2* __restrict__ f) {
    int l = threadIdx.x & 31;
    int line = blockIdx.x * 8 + (threadIdx.x >> 5);
    size_t base = (size_t)line * HH;
    float2 v[16];
#pragma unroll
    for (int r = 0; r < 16; r++) v[r] = f[base + 32 * r + l];
    wfft_inv(v, l);
    const float S = 1.0f / 512.0f;
#pragma unroll
    for (int j = 0; j < 16; j++)
        f[base + 32 * j + l] = make_float2(v[j].x * S, v[j].y * S);
}

// ---------------- column pass: 8 cols/block, 1 warp = 1 column ----------------
// smem only for transpose staging: 8 * CSTR float2 = 32,896 B

__global__ void __launch_bounds__(256, 2) k_col(float2* __restrict__ f, int det) {
    extern __shared__ float2 T[];
    int img = blockIdx.x >> 6;                 // 64 tiles per image
    int c0 = (blockIdx.x & 63) << 3;
    int w = img % 3;
    float2* base = f + (size_t)img * (HH * HH);

    int colL = threadIdx.x & 7;                // staging map: warp = 4 rows x 8 cols
    int rowq = threadIdx.x >> 3;               // 0..31
#pragma unroll 4
    for (int it = 0; it < 16; it++) {
        int r = it * 32 + rowq;
        T[colL * CSTR + r] = base[(size_t)r * HH + c0 + colL];
    }
    __syncthreads();

    int wid = threadIdx.x >> 5;                // warp -> column
    int l = threadIdx.x & 31;
    float2* t = T + wid * CSTR;
    float2 v[16];
#pragma unroll
    for (int j = 0; j < 16; j++) v[j] = t[32 * j + l];
    wfft_fwd(v, l);
    const float2* Hc = (det ? d_HD : d_HL) +
                       ((size_t)w * HH + (c0 + wid)) * HH;   // permuted table
#pragma unroll
    for (int r = 0; r < 16; r++) v[r] = cmulf(v[r], Hc[32 * r + l]);
    wfft_inv(v, l);
#pragma unroll
    for (int j = 0; j < 16; j++) t[32 * j + l] = v[j];
    __syncthreads();

#pragma unroll 4
    for (int it = 0; it < 16; it++) {
        int r = it * 32 + rowq;
        base[(size_t)r * HH + c0 + colL] = T[colL * CSTR + r];
    }
}

// ---------------- launch ----------------
// Chain: k_first | repeat l=0..4: k_col(HL), (l<4: k_rowmid(l+1)) | k_col(HD) | k_last
extern "C" void kernel_launch(void* const* d_in, const int* in_sizes, int n_in,
                              void* d_out, int out_size) {
    const float* xr = (const float*)d_in[0];
    const float* xi = (const float*)d_in[1];
    const float* pm = (const float*)d_in[2];
    float2* f = (float2*)d_out;

    const int COLSMEM = 8 * CSTR * (int)sizeof(float2);   // 32,896 B

    k_initH<<<(NWL * HH * HH + 255) / 256, 256>>>();
    k_initP<<<(NLAY * NWL * HH * HH + 255) / 256, 256>>>(pm);

    const int ROWBLKS = NIMG * HH / 8;         // 4608
    const int COLBLKS = NIMG * (HH / 8);       // 4608

    k_first<<<ROWBLKS, 256>>>(xr, xi, f);
    for (int l = 0; l < NLAY; l++) {
        k_col<<<COLBLKS, 256, COLSMEM>>>(f, 0);
        if (l < NLAY - 1) k_rowmid<<<ROWBLKS, 256>>>(f, l + 1);
    }
    k_col<<<COLBLKS, 256, COLSMEM>>>(f, 1);
    k_last<<<ROWBLKS, 256>>>(f);
}

// round 7
// speedup vs baseline: 1.2459x; 1.2459x over previous
#include <cuda_runtime.h>
#include <math.h>

#define HH    512
#define NIMG  72          // B(8)*M(3)*W(3); wavelength = img % 3
#define NWL   3
#define NLAY  5
#define TWO_PI 6.2831853071795864769f

#define LPLANE 528        // row-kernel per-line exchange plane (float2), >= 527
#define CPLANE 529        // k_col per-column plane (odd float2 stride for staging banks)

// Storage-slot -> spectral-index map of the 16x32 warp-group FFT.
#define KMAP(s) (((s) & 15) | ((((s) >> 8) & 1) << 4) | ((((s) >> 4) & 15) << 5))

// -------- precomputed tables (__device__ globals = sanctioned scratch) --------
// H stored permuted on BOTH axes by KMAP; P natural.
__device__ float2 d_HL[NWL * HH * HH];
__device__ float2 d_HD[NWL * HH * HH];
__device__ float2 d_expP[NLAY * NWL * HH * HH];

__device__ __forceinline__ float2 cmulf(float2 a, float2 b) {
    return make_float2(a.x * b.x - a.y * b.y, a.x * b.y + a.y * b.x);
}
template <int SGN>
__device__ __forceinline__ float2 muli(float2 z) {
    return (SGN > 0) ? make_float2(-z.y, z.x) : make_float2(z.y, -z.x);
}
__device__ __forceinline__ int taud(int k) { return (k < 8) ? 2 * k : 2 * (k - 8) + 1; }
__device__ __forceinline__ int alp(int i) {
    return ((i & 7) << 2) | (((i >> 3) & 1) << 1) | (i >> 4);
}

// natural-order 8-point DFT (in place)
template <int SGN>
__device__ __forceinline__ void dft8(float2 v[8]) {
    const float C = 0.70710678118654752f;
    const float sg = (float)SGN;
    float2 t0 = make_float2(v[0].x + v[4].x, v[0].y + v[4].y);
    float2 t1 = make_float2(v[0].x - v[4].x, v[0].y - v[4].y);
    float2 t2 = make_float2(v[2].x + v[6].x, v[2].y + v[6].y);
    float2 t3 = make_float2(v[2].x - v[6].x, v[2].y - v[6].y);
    float2 u0 = make_float2(v[1].x + v[5].x, v[1].y + v[5].y);
    float2 u1 = make_float2(v[1].x - v[5].x, v[1].y - v[5].y);
    float2 u2 = make_float2(v[3].x + v[7].x, v[3].y + v[7].y);
    float2 u3 = make_float2(v[3].x - v[7].x, v[3].y - v[7].y);
    float2 it3 = muli<SGN>(t3);
    float2 iu3 = muli<SGN>(u3);
    float2 E0 = make_float2(t0.x + t2.x, t0.y + t2.y);
    float2 E2 = make_float2(t0.x - t2.x, t0.y - t2.y);
    float2 E1 = make_float2(t1.x + it3.x, t1.y + it3.y);
    float2 E3 = make_float2(t1.x - it3.x, t1.y - it3.y);
    float2 O0 = make_float2(u0.x + u2.x, u0.y + u2.y);
    float2 O2 = make_float2(u0.x - u2.x, u0.y - u2.y);
    float2 O1 = make_float2(u1.x + iu3.x, u1.y + iu3.y);
    float2 O3 = make_float2(u1.x - iu3.x, u1.y - iu3.y);
    float2 w1o = make_float2(C * (O1.x - sg * O1.y), C * (O1.y + sg * O1.x));
    float2 w2o = muli<SGN>(O2);
    float2 w3o = make_float2(-C * (O3.x + sg * O3.y), C * (sg * O3.x - O3.y));
    v[0] = make_float2(E0.x + O0.x, E0.y + O0.y);
    v[4] = make_float2(E0.x - O0.x, E0.y - O0.y);
    v[1] = make_float2(E1.x + w1o.x, E1.y + w1o.y);
    v[5] = make_float2(E1.x - w1o.x, E1.y - w1o.y);
    v[2] = make_float2(E2.x + w2o.x, E2.y + w2o.y);
    v[6] = make_float2(E2.x - w2o.x, E2.y - w2o.y);
    v[3] = make_float2(E3.x + w3o.x, E3.y + w3o.y);
    v[7] = make_float2(E3.x - w3o.x, E3.y - w3o.y);
}

#define CC16_0 1.0f
#define CC16_1 0.92387953251128674f
#define CC16_2 0.70710678118654752f
#define CC16_3 0.38268343236508977f

// DIT-16: input v[k] = in[taud(k)], output natural.
template <int SGN>
__device__ __forceinline__ void dit16(float2 v[16]) {
    const float CC[8] = {CC16_0, CC16_1, CC16_2, CC16_3, 0.f, -CC16_3, -CC16_2, -CC16_1};
    const float SS[8] = {0.f, CC16_3, CC16_2, CC16_1, 1.f, CC16_1, CC16_2, CC16_3};
    dft8<SGN>(v);
    dft8<SGN>(v + 8);
#pragma unroll
    for (int r = 0; r < 8; r++) {
        float2 w = make_float2(CC[r], (float)SGN * SS[r]);
        float2 t = cmulf(v[8 + r], w);
        v[8 + r] = make_float2(v[r].x - t.x, v[r].y - t.y);
        v[r]     = make_float2(v[r].x + t.x, v[r].y + t.y);
    }
}

// DIF-16: natural input, output v[r] = X[taud(r)].
template <int SGN>
__device__ __forceinline__ void dif16(float2 v[16]) {
    const float CC[8] = {CC16_0, CC16_1, CC16_2, CC16_3, 0.f, -CC16_3, -CC16_2, -CC16_1};
    const float SS[8] = {0.f, CC16_3, CC16_2, CC16_1, 1.f, CC16_1, CC16_2, CC16_3};
#pragma unroll
    for (int r = 0; r < 8; r++) {
        float2 a = v[r], b = v[8 + r];
        v[r] = make_float2(a.x + b.x, a.y + b.y);
        float2 d = make_float2(a.x - b.x, a.y - b.y);
        float2 w = make_float2(CC[r], (float)SGN * SS[r]);
        v[8 + r] = cmulf(d, w);
    }
    dft8<SGN>(v);
    dft8<SGN>(v + 8);
}

#define C32_1 0.98078528040323044f
#define C32_2 0.92387953251128674f
#define C32_3 0.83146961230254524f
#define C32_4 0.70710678118654752f
#define C32_5 0.55557023301960222f
#define C32_6 0.38268343236508977f
#define C32_7 0.19509032201612827f

// DIT-32: input v[i] = in[alp(i)], output natural.
template <int SGN>
__device__ __forceinline__ void dit32(float2 v[32]) {
    const float C[16] = {1.f, C32_1, C32_2, C32_3, C32_4, C32_5, C32_6, C32_7,
                         0.f, -C32_7, -C32_6, -C32_5, -C32_4, -C32_3, -C32_2, -C32_1};
    const float S[16] = {0.f, C32_7, C32_6, C32_5, C32_4, C32_3, C32_2, C32_1,
                         1.f, C32_1, C32_2, C32_3, C32_4, C32_5, C32_6, C32_7};
    dit16<SGN>(v);
    dit16<SGN>(v + 16);
#pragma unroll
    for (int r = 0; r < 16; r++) {
        float2 w = make_float2(C[r], (float)SGN * S[r]);
        float2 t = cmulf(v[16 + r], w);
        v[16 + r] = make_float2(v[r].x - t.x, v[r].y - t.y);
        v[r]      = make_float2(v[r].x + t.x, v[r].y + t.y);
    }
}

// DIF-32: natural input, output v[r] = X[alp(r)].
template <int SGN>
__device__ __forceinline__ void dif32(float2 v[32]) {
    const float C[16] = {1.f, C32_1, C32_2, C32_3, C32_4, C32_5, C32_6, C32_7,
                         0.f, -C32_7, -C32_6, -C32_5, -C32_4, -C32_3, -C32_2, -C32_1};
    const float S[16] = {0.f, C32_7, C32_6, C32_5, C32_4, C32_3, C32_2, C32_1,
                         1.f, C32_1, C32_2, C32_3, C32_4, C32_5, C32_6, C32_7};
#pragma unroll
    for (int r = 0; r < 16; r++) {
        float2 a = v[r], b = v[16 + r];
        v[r] = make_float2(a.x + b.x, a.y + b.y);
        float2 d = make_float2(a.x - b.x, a.y - b.y);
        float2 w = make_float2(C[r], (float)SGN * S[r]);
        v[16 + r] = cmulf(d, w);
    }
    dif16<SGN>(v);
    dif16<SGN>(v + 16);
}

// v[r] *= W512^{SGN * t * alp(r)}
template <int SGN>
__device__ __forceinline__ void twid_alp(float2 v[32], int t) {
    float s, c;
    __sincosf((float)SGN * TWO_PI * (float)t * (1.0f / 512.0f), &s, &c);
    float2 w1 = make_float2(c, s);
    float2 w2 = cmulf(w1, w1);
    float2 w3 = cmulf(w2, w1);
    float2 w4 = cmulf(w2, w2);
    float2 bases[4];
    bases[0] = make_float2(1.f, 0.f); bases[1] = w2; bases[2] = w1; bases[3] = w3;
#pragma unroll
    for (int g = 0; g < 4; g++) {
        float2 tw = bases[g];
#pragma unroll
        for (int k = 0; k < 8; k++) {
            int r = g * 8 + k;
            if (!(g == 0 && k == 0)) v[r] = cmulf(v[r], tw);
            if (k < 7) tw = cmulf(tw, w4);
        }
    }
}

// v[k] *= W512^{SGN * m * taud(k)}, k = 0..15
template <int SGN>
__device__ __forceinline__ void twid_tau(float2* v, int m) {
    float s, c;
    __sincosf((float)SGN * TWO_PI * (float)m * (1.0f / 512.0f), &s, &c);
    float2 w1 = make_float2(c, s);
    float2 w2 = cmulf(w1, w1);
    float2 tw = w2;
#pragma unroll
    for (int k = 1; k < 8; k++) { v[k] = cmulf(v[k], tw); tw = cmulf(tw, w2); }
    tw = w1;
#pragma unroll
    for (int k = 8; k < 16; k++) { v[k] = cmulf(v[k], tw); tw = cmulf(tw, w2); }
}

// forward 512-pt group FFT (16 threads, 1 exchange):
// in: v[a] = x[16a + t] (natural). out: v[c] = X[t + 32c], v[16+c] = X[t+16+32c].
__device__ __forceinline__ void gfwd(float2 v[32], float2* pl, int t) {
    dif32<-1>(v);
    twid_alp<-1>(v, t);
    __syncwarp();
#pragma unroll
    for (int r = 0; r < 32; r++) pl[alp(r) + 33 * t] = v[r];
    __syncwarp();
#pragma unroll
    for (int k = 0; k < 16; k++) v[k]      = pl[t      + 33 * taud(k)];
#pragma unroll
    for (int k = 0; k < 16; k++) v[16 + k] = pl[t + 16 + 33 * taud(k)];
    dit16<-1>(v);
    dit16<-1>(v + 16);
}

// inverse 512-pt group FFT (unnormalized):
// in: v[c] = Y[t + 32c], v[16+c] = Y[t+16+32c]. out: v[a] = 512 * x[16a + t].
__device__ __forceinline__ void ginv(float2 v[32], float2* pl, int t) {
    dif16<1>(v);
    dif16<1>(v + 16);
    twid_tau<1>(v, t);
    twid_tau<1>(v + 16, t + 16);
    __syncwarp();
#pragma unroll
    for (int k = 0; k < 16; k++) pl[t      + 33 * taud(k)] = v[k];
#pragma unroll
    for (int k = 0; k < 16; k++) pl[t + 16 + 33 * taud(k)] = v[16 + k];
    __syncwarp();
#pragma unroll
    for (int r = 0; r < 32; r++) v[r] = pl[alp(r) + 33 * t];
    dit32<1>(v);
}

// ---------------- init kernels ----------------

__global__ void __launch_bounds__(256) k_initH() {
    int idx = blockIdx.x * 256 + threadIdx.x;
    if (idx >= NWL * HH * HH) return;
    int w = idx / (HH * HH);
    int xs = (idx >> 9) & 511;
    int j = idx & 511;
    int r = KMAP(xs);
    int c = KMAP(j);
    const float wls[3] = {5.32e-07f, 6.33e-07f, 8.5e-07f};
    const float TW = TWO_PI;
    float mr = (float)((r < 256) ? r : r - 512);
    float mc = (float)((c < 256) ? c : c - 512);
    double invnd = 1.0 / (512.0 * 8e-06);
    float fr = (float)((double)mr * invnd);
    float fc = (float)((double)mc * invnd);
    float kx = __fmul_rn(TW, fr);
    float ky = __fmul_rn(TW, fc);
    float kk = __fdiv_rn(TW, wls[w]);
    float arg = __fsub_rn(__fsub_rn(__fmul_rn(kk, kk), __fmul_rn(kx, kx)),
                          __fmul_rn(ky, ky));
    const float SL = 1.0f / 512.0f;
    const float SD = 1.0f / 512.0f;   // 11 factors total
    float2 hl, hd;
    if (arg >= 0.0f) {
        float kz = __fsqrt_rn(arg);
        float thL = __fmul_rn(kz, 0.03f);
        float thD = __fmul_rn(kz, 0.1f);
        double sl, cl, sd, cd;
        sincos((double)thL, &sl, &cl);
        sincos((double)thD, &sd, &cd);
        hl = make_float2((float)cl * SL, (float)sl * SL);
        hd = make_float2((float)cd * SD, (float)sd * SD);
    } else {
        float a = __fsqrt_rn(-arg);
        hl = make_float2(expf(-__fmul_rn(a, 0.03f)) * SL, 0.0f);
        hd = make_float2(expf(-__fmul_rn(a, 0.1f)) * SD, 0.0f);
    }
    d_HL[idx] = hl;
    d_HD[idx] = hd;
}

__global__ void __launch_bounds__(256) k_initP(const float* __restrict__ pm) {
    int idx = blockIdx.x * 256 + threadIdx.x;
    if (idx >= NLAY * NWL * HH * HH) return;
    float p = pm[idx];
    float s, c;
    __sincosf(p, &s, &c);
    int layer = idx / (NWL * HH * HH);
    float sc = (layer == 0) ? 1.0f : (1.0f / 512.0f);
    d_expP[idx] = make_float2(c * sc, s * sc);
}

// ---------------- row kernels: 16 threads/line, 16 lines/block, warp-private ----------------

__global__ void __launch_bounds__(256, 2) k_first(const float* __restrict__ xr,
                                                  const float* __restrict__ xi,
                                                  float2* __restrict__ f) {
    extern __shared__ float2 sm[];
    int t = threadIdx.x & 15, li = threadIdx.x >> 4;
    int line = blockIdx.x * 16 + li;
    int img = line >> 9, y = line & 511, w = img % 3;
    const float2* P = d_expP + ((size_t)w * HH + y) * HH;   // layer 0, natural
    size_t base = (size_t)line * HH;
    float2* pl = sm + li * LPLANE;
    float2 v[32];
#pragma unroll
    for (int a = 0; a < 32; a++) {
        int x = 16 * a + t;
        float2 z = make_float2(xr[base + x], xi[base + x]);
        v[a] = cmulf(z, P[x]);
    }
    gfwd(v, pl, t);
#pragma unroll
    for (int r = 0; r < 32; r++) f[base + 16 * r + t] = v[r];
}

__global__ void __launch_bounds__(256, 2) k_rowmid(float2* __restrict__ f, int layer) {
    extern __shared__ float2 sm[];
    int t = threadIdx.x & 15, li = threadIdx.x >> 4;
    int line = blockIdx.x * 16 + li;
    int img = line >> 9, y = line & 511, w = img % 3;
    const float2* P = d_expP + (((size_t)layer * NWL + w) * HH + y) * HH;
    size_t base = (size_t)line * HH;
    float2* pl = sm + li * LPLANE;
    float2 v[32];
#pragma unroll
    for (int r = 0; r < 32; r++) v[r] = f[base + 16 * r + t];
    ginv(v, pl, t);
#pragma unroll
    for (int a = 0; a < 32; a++) v[a] = cmulf(v[a], P[16 * a + t]);
    gfwd(v, pl, t);
#pragma unroll
    for (int r = 0; r < 32; r++) f[base + 16 * r + t] = v[r];
}

__global__ void __launch_bounds__(256, 2) k_last(float2* __restrict__ f) {
    extern __shared__ float2 sm[];
    int t = threadIdx.x & 15, li = threadIdx.x >> 4;
    int line = blockIdx.x * 16 + li;
    size_t base = (size_t)line * HH;
    float2* pl = sm + li * LPLANE;
    float2 v[32];
#pragma unroll
    for (int r = 0; r < 32; r++) v[r] = f[base + 16 * r + t];
    ginv(v, pl, t);
    const float S = 1.0f / 512.0f;
#pragma unroll
    for (int a = 0; a < 32; a++)
        f[base + 16 * a + t] = make_float2(v[a].x * S, v[a].y * S);
}

// ---------------- column pass: 16 cols/block, 16 threads/col ----------------

__global__ void __launch_bounds__(256, 2) k_col(float2* __restrict__ f, int det) {
    extern __shared__ float2 T[];
    int img = blockIdx.x >> 5;
    int c0 = (blockIdx.x & 31) << 4;
    int w = img % 3;
    float2* base = f + (size_t)img * (HH * HH);

    int colL = threadIdx.x & 15, rowq = threadIdx.x >> 4;
#pragma unroll 4
    for (int it = 0; it < 32; it++) {
        int r = it * 16 + rowq;
        T[colL * CPLANE + r] = base[(size_t)r * HH + c0 + colL];
    }
    __syncthreads();

    int g = threadIdx.x >> 4, t = threadIdx.x & 15;
    float2* pl = T + g * CPLANE;
    float2 v[32];
#pragma unroll
    for (int a = 0; a < 32; a++) v[a] = pl[16 * a + t];
    gfwd(v, pl, t);
    const float2* Hc = (det ? d_HD : d_HL) + ((size_t)w * HH + (c0 + g)) * HH;
#pragma unroll
    for (int r = 0; r < 32; r++) v[r] = cmulf(v[r], Hc[16 * r + t]);
    ginv(v, pl, t);
    __syncwarp();
#pragma unroll
    for (int a = 0; a < 32; a++) pl[16 * a + t] = v[a];
    __syncthreads();

#pragma unroll 4
    for (int it = 0; it < 32; it++) {
        int r = it * 16 + rowq;
        base[(size_t)r * HH + c0 + colL] = T[colL * CPLANE + r];
    }
}

// ---------------- launch ----------------
// Chain: k_first | repeat l=0..4: k_col(HL), (l<4: k_rowmid(l+1)) | k_col(HD) | k_last
extern "C" void kernel_launch(void* const* d_in, const int* in_sizes, int n_in,
                              void* d_out, int out_size) {
    const float* xr = (const float*)d_in[0];
    const float* xi = (const float*)d_in[1];
    const float* pm = (const float*)d_in[2];
    float2* f = (float2*)d_out;

    const int ROWSMEM = 16 * LPLANE * (int)sizeof(float2);   // 67,584 B
    const int COLSMEM = 16 * CPLANE * (int)sizeof(float2);   // 67,712 B
    cudaFuncSetAttribute(k_first,  cudaFuncAttributeMaxDynamicSharedMemorySize, ROWSMEM);
    cudaFuncSetAttribute(k_rowmid, cudaFuncAttributeMaxDynamicSharedMemorySize, ROWSMEM);
    cudaFuncSetAttribute(k_last,   cudaFuncAttributeMaxDynamicSharedMemorySize, ROWSMEM);
    cudaFuncSetAttribute(k_col,    cudaFuncAttributeMaxDynamicSharedMemorySize, COLSMEM);

    k_initH<<<(NWL * HH * HH + 255) / 256, 256>>>();
    k_initP<<<(NLAY * NWL * HH * HH + 255) / 256, 256>>>(pm);

    const int ROWBLKS = NIMG * HH / 16;        // 2304
    const int COLBLKS = NIMG * (HH / 16);      // 2304

    k_first<<<ROWBLKS, 256, ROWSMEM>>>(xr, xi, f);
    for (int l = 0; l < NLAY; l++) {
        k_col<<<COLBLKS, 256, COLSMEM>>>(f, 0);
        if (l < NLAY - 1) k_rowmid<<<ROWBLKS, 256, ROWSMEM>>>(f, l + 1);
    }
    k_col<<<COLBLKS, 256, COLSMEM>>>(f, 1);
    k_last<<<ROWBLKS, 256, ROWSMEM>>>(f);
}

// round 8
// speedup vs baseline: 1.6191x; 1.2995x over previous
#include <cuda_runtime.h>
#include <math.h>

#define HH    512
#define NIMG  72          // B(8)*M(3)*W(3); wavelength = img % 3
#define NWL   3
#define NLAY  5
#define TWO_PI 6.2831853071795864769f

#define LPLANE 528        // row-kernel per-line exchange plane (float2), >= 527
#define CPLANE 529        // k_col per-column plane (odd float2 stride for staging banks)

// Storage-slot -> spectral-index map of the 16x32 warp-group FFT.
#define KMAP(s) (((s) & 15) | ((((s) >> 8) & 1) << 4) | ((((s) >> 4) & 15) << 5))

// -------- precomputed tables (__device__ globals = sanctioned scratch) --------
__device__ float2 d_HL[NWL * HH * HH];
__device__ float2 d_HD[NWL * HH * HH];
__device__ float2 d_expP[NLAY * NWL * HH * HH];

__device__ __forceinline__ float2 cmulf(float2 a, float2 b) {
    return make_float2(a.x * b.x - a.y * b.y, a.x * b.y + a.y * b.x);
}
template <int SGN>
__device__ __forceinline__ float2 muli(float2 z) {
    return (SGN > 0) ? make_float2(-z.y, z.x) : make_float2(z.y, -z.x);
}
__device__ __forceinline__ int taud(int k) { return (k < 8) ? 2 * k : 2 * (k - 8) + 1; }
__device__ __forceinline__ int alp(int i) {
    return ((i & 7) << 2) | (((i >> 3) & 1) << 1) | (i >> 4);
}

__device__ __forceinline__ void cpasync8(void* smem, const void* g) {
    unsigned s = (unsigned)__cvta_generic_to_shared(smem);
    asm volatile("cp.async.ca.shared.global [%0], [%1], 8;" :: "r"(s), "l"(g) : "memory");
}
__device__ __forceinline__ void cpcommit() {
    asm volatile("cp.async.commit_group;" ::: "memory");
}
__device__ __forceinline__ void cpwait0() {
    asm volatile("cp.async.wait_group 0;" ::: "memory");
}

// natural-order 8-point DFT (in place)
template <int SGN>
__device__ __forceinline__ void dft8(float2 v[8]) {
    const float C = 0.70710678118654752f;
    const float sg = (float)SGN;
    float2 t0 = make_float2(v[0].x + v[4].x, v[0].y + v[4].y);
    float2 t1 = make_float2(v[0].x - v[4].x, v[0].y - v[4].y);
    float2 t2 = make_float2(v[2].x + v[6].x, v[2].y + v[6].y);
    float2 t3 = make_float2(v[2].x - v[6].x, v[2].y - v[6].y);
    float2 u0 = make_float2(v[1].x + v[5].x, v[1].y + v[5].y);
    float2 u1 = make_float2(v[1].x - v[5].x, v[1].y - v[5].y);
    float2 u2 = make_float2(v[3].x + v[7].x, v[3].y + v[7].y);
    float2 u3 = make_float2(v[3].x - v[7].x, v[3].y - v[7].y);
    float2 it3 = muli<SGN>(t3);
    float2 iu3 = muli<SGN>(u3);
    float2 E0 = make_float2(t0.x + t2.x, t0.y + t2.y);
    float2 E2 = make_float2(t0.x - t2.x, t0.y - t2.y);
    float2 E1 = make_float2(t1.x + it3.x, t1.y + it3.y);
    float2 E3 = make_float2(t1.x - it3.x, t1.y - it3.y);
    float2 O0 = make_float2(u0.x + u2.x, u0.y + u2.y);
    float2 O2 = make_float2(u0.x - u2.x, u0.y - u2.y);
    float2 O1 = make_float2(u1.x + iu3.x, u1.y + iu3.y);
    float2 O3 = make_float2(u1.x - iu3.x, u1.y - iu3.y);
    float2 w1o = make_float2(C * (O1.x - sg * O1.y), C * (O1.y + sg * O1.x));
    float2 w2o = muli<SGN>(O2);
    float2 w3o = make_float2(-C * (O3.x + sg * O3.y), C * (sg * O3.x - O3.y));
    v[0] = make_float2(E0.x + O0.x, E0.y + O0.y);
    v[4] = make_float2(E0.x - O0.x, E0.y - O0.y);
    v[1] = make_float2(E1.x + w1o.x, E1.y + w1o.y);
    v[5] = make_float2(E1.x - w1o.x, E1.y - w1o.y);
    v[2] = make_float2(E2.x + w2o.x, E2.y + w2o.y);
    v[6] = make_float2(E2.x - w2o.x, E2.y - w2o.y);
    v[3] = make_float2(E3.x + w3o.x, E3.y + w3o.y);
    v[7] = make_float2(E3.x - w3o.x, E3.y - w3o.y);
}

#define CC16_1 0.92387953251128674f
#define CC16_2 0.70710678118654752f
#define CC16_3 0.38268343236508977f

template <int SGN>
__device__ __forceinline__ void dit16(float2 v[16]) {
    const float CC[8] = {1.f, CC16_1, CC16_2, CC16_3, 0.f, -CC16_3, -CC16_2, -CC16_1};
    const float SS[8] = {0.f, CC16_3, CC16_2, CC16_1, 1.f, CC16_1, CC16_2, CC16_3};
    dft8<SGN>(v);
    dft8<SGN>(v + 8);
#pragma unroll
    for (int r = 0; r < 8; r++) {
        float2 w = make_float2(CC[r], (float)SGN * SS[r]);
        float2 t = cmulf(v[8 + r], w);
        v[8 + r] = make_float2(v[r].x - t.x, v[r].y - t.y);
        v[r]     = make_float2(v[r].x + t.x, v[r].y + t.y);
    }
}

template <int SGN>
__device__ __forceinline__ void dif16(float2 v[16]) {
    const float CC[8] = {1.f, CC16_1, CC16_2, CC16_3, 0.f, -CC16_3, -CC16_2, -CC16_1};
    const float SS[8] = {0.f, CC16_3, CC16_2, CC16_1, 1.f, CC16_1, CC16_2, CC16_3};
#pragma unroll
    for (int r = 0; r < 8; r++) {
        float2 a = v[r], b = v[8 + r];
        v[r] = make_float2(a.x + b.x, a.y + b.y);
        float2 d = make_float2(a.x - b.x, a.y - b.y);
        float2 w = make_float2(CC[r], (float)SGN * SS[r]);
        v[8 + r] = cmulf(d, w);
    }
    dft8<SGN>(v);
    dft8<SGN>(v + 8);
}

#define C32_1 0.98078528040323044f
#define C32_2 0.92387953251128674f
#define C32_3 0.83146961230254524f
#define C32_4 0.70710678118654752f
#define C32_5 0.55557023301960222f
#define C32_6 0.38268343236508977f
#define C32_7 0.19509032201612827f

template <int SGN>
__device__ __forceinline__ void dit32(float2 v[32]) {
    const float C[16] = {1.f, C32_1, C32_2, C32_3, C32_4, C32_5, C32_6, C32_7,
                         0.f, -C32_7, -C32_6, -C32_5, -C32_4, -C32_3, -C32_2, -C32_1};
    const float S[16] = {0.f, C32_7, C32_6, C32_5, C32_4, C32_3, C32_2, C32_1,
                         1.f, C32_1, C32_2, C32_3, C32_4, C32_5, C32_6, C32_7};
    dit16<SGN>(v);
    dit16<SGN>(v + 16);
#pragma unroll
    for (int r = 0; r < 16; r++) {
        float2 w = make_float2(C[r], (float)SGN * S[r]);
        float2 t = cmulf(v[16 + r], w);
        v[16 + r] = make_float2(v[r].x - t.x, v[r].y - t.y);
        v[r]      = make_float2(v[r].x + t.x, v[r].y + t.y);
    }
}

template <int SGN>
__device__ __forceinline__ void dif32(float2 v[32]) {
    const float C[16] = {1.f, C32_1, C32_2, C32_3, C32_4, C32_5, C32_6, C32_7,
                         0.f, -C32_7, -C32_6, -C32_5, -C32_4, -C32_3, -C32_2, -C32_1};
    const float S[16] = {0.f, C32_7, C32_6, C32_5, C32_4, C32_3, C32_2, C32_1,
                         1.f, C32_1, C32_2, C32_3, C32_4, C32_5, C32_6, C32_7};
#pragma unroll
    for (int r = 0; r < 16; r++) {
        float2 a = v[r], b = v[16 + r];
        v[r] = make_float2(a.x + b.x, a.y + b.y);
        float2 d = make_float2(a.x - b.x, a.y - b.y);
        float2 w = make_float2(C[r], (float)SGN * S[r]);
        v[16 + r] = cmulf(d, w);
    }
    dif16<SGN>(v);
    dif16<SGN>(v + 16);
}

template <int SGN>
__device__ __forceinline__ void twid_alp(float2 v[32], int t) {
    float s, c;
    __sincosf((float)SGN * TWO_PI * (float)t * (1.0f / 512.0f), &s, &c);
    float2 w1 = make_float2(c, s);
    float2 w2 = cmulf(w1, w1);
    float2 w3 = cmulf(w2, w1);
    float2 w4 = cmulf(w2, w2);
    float2 bases[4];
    bases[0] = make_float2(1.f, 0.f); bases[1] = w2; bases[2] = w1; bases[3] = w3;
#pragma unroll
    for (int g = 0; g < 4; g++) {
        float2 tw = bases[g];
#pragma unroll
        for (int k = 0; k < 8; k++) {
            int r = g * 8 + k;
            if (!(g == 0 && k == 0)) v[r] = cmulf(v[r], tw);
            if (k < 7) tw = cmulf(tw, w4);
        }
    }
}

template <int SGN>
__device__ __forceinline__ void twid_tau(float2* v, int m) {
    float s, c;
    __sincosf((float)SGN * TWO_PI * (float)m * (1.0f / 512.0f), &s, &c);
    float2 w1 = make_float2(c, s);
    float2 w2 = cmulf(w1, w1);
    float2 tw = w2;
#pragma unroll
    for (int k = 1; k < 8; k++) { v[k] = cmulf(v[k], tw); tw = cmulf(tw, w2); }
    tw = w1;
#pragma unroll
    for (int k = 8; k < 16; k++) { v[k] = cmulf(v[k], tw); tw = cmulf(tw, w2); }
}

// forward 512-pt group FFT (16 threads, 1 exchange)
__device__ __forceinline__ void gfwd(float2 v[32], float2* pl, int t) {
    dif32<-1>(v);
    twid_alp<-1>(v, t);
    __syncwarp();
#pragma unroll
    for (int r = 0; r < 32; r++) pl[alp(r) + 33 * t] = v[r];
    __syncwarp();
#pragma unroll
    for (int k = 0; k < 16; k++) v[k]      = pl[t      + 33 * taud(k)];
#pragma unroll
    for (int k = 0; k < 16; k++) v[16 + k] = pl[t + 16 + 33 * taud(k)];
    dit16<-1>(v);
    dit16<-1>(v + 16);
}

// inverse 512-pt group FFT (unnormalized)
__device__ __forceinline__ void ginv(float2 v[32], float2* pl, int t) {
    dif16<1>(v);
    dif16<1>(v + 16);
    twid_tau<1>(v, t);
    twid_tau<1>(v + 16, t + 16);
    __syncwarp();
#pragma unroll
    for (int k = 0; k < 16; k++) pl[t      + 33 * taud(k)] = v[k];
#pragma unroll
    for (int k = 0; k < 16; k++) pl[t + 16 + 33 * taud(k)] = v[16 + k];
    __syncwarp();
#pragma unroll
    for (int r = 0; r < 32; r++) v[r] = pl[alp(r) + 33 * t];
    dit32<1>(v);
}

// ---------------- init kernels ----------------

__global__ void __launch_bounds__(256) k_initH() {
    int idx = blockIdx.x * 256 + threadIdx.x;
    if (idx >= NWL * HH * HH) return;
    int w = idx / (HH * HH);
    int xs = (idx >> 9) & 511;
    int j = idx & 511;
    int r = KMAP(xs);
    int c = KMAP(j);
    const float wls[3] = {5.32e-07f, 6.33e-07f, 8.5e-07f};
    const float TW = TWO_PI;
    float mr = (float)((r < 256) ? r : r - 512);
    float mc = (float)((c < 256) ? c : c - 512);
    double invnd = 1.0 / (512.0 * 8e-06);
    float fr = (float)((double)mr * invnd);
    float fc = (float)((double)mc * invnd);
    float kx = __fmul_rn(TW, fr);
    float ky = __fmul_rn(TW, fc);
    float kk = __fdiv_rn(TW, wls[w]);
    float arg = __fsub_rn(__fsub_rn(__fmul_rn(kk, kk), __fmul_rn(kx, kx)),
                          __fmul_rn(ky, ky));
    const float SL = 1.0f / 512.0f;
    const float SD = 1.0f / 512.0f;   // 11 factors total
    float2 hl, hd;
    if (arg >= 0.0f) {
        float kz = __fsqrt_rn(arg);
        float thL = __fmul_rn(kz, 0.03f);
        float thD = __fmul_rn(kz, 0.1f);
        double sl, cl, sd, cd;
        sincos((double)thL, &sl, &cl);
        sincos((double)thD, &sd, &cd);
        hl = make_float2((float)cl * SL, (float)sl * SL);
        hd = make_float2((float)cd * SD, (float)sd * SD);
    } else {
        float a = __fsqrt_rn(-arg);
        hl = make_float2(expf(-__fmul_rn(a, 0.03f)) * SL, 0.0f);
        hd = make_float2(expf(-__fmul_rn(a, 0.1f)) * SD, 0.0f);
    }
    d_HL[idx] = hl;
    d_HD[idx] = hd;
}

__global__ void __launch_bounds__(256) k_initP(const float* __restrict__ pm) {
    int idx = blockIdx.x * 256 + threadIdx.x;
    if (idx >= NLAY * NWL * HH * HH) return;
    float p = pm[idx];
    float s, c;
    __sincosf(p, &s, &c);
    int layer = idx / (NWL * HH * HH);
    float sc = (layer == 0) ? 1.0f : (1.0f / 512.0f);
    d_expP[idx] = make_float2(c * sc, s * sc);
}

// ---------------- row kernels: 16 threads/line, 16 lines/block ----------------

__global__ void __launch_bounds__(256, 2) k_first(const float* __restrict__ xr,
                                                  const float* __restrict__ xi,
                                                  float2* __restrict__ f) {
    extern __shared__ float2 sm[];
    int t = threadIdx.x & 15, li = threadIdx.x >> 4;
    int line = blockIdx.x * 16 + li;
    int img = line >> 9, y = line & 511, w = img % 3;
    const float2* P = d_expP + ((size_t)w * HH + y) * HH;   // layer 0, natural
    size_t base = (size_t)line * HH;
    float2* pl = sm + li * LPLANE;
    float2 v[32];
#pragma unroll
    for (int a = 0; a < 32; a++) {
        int x = 16 * a + t;
        float2 z = make_float2(xr[base + x], xi[base + x]);
        v[a] = cmulf(z, P[x]);
    }
    gfwd(v, pl, t);
#pragma unroll
    for (int r = 0; r < 32; r++) f[base + 16 * r + t] = v[r];
}

__global__ void __launch_bounds__(256, 2) k_rowmid(float2* __restrict__ f, int layer) {
    extern __shared__ float2 sm[];
    int t = threadIdx.x & 15, li = threadIdx.x >> 4;
    int line = blockIdx.x * 16 + li;
    int img = line >> 9, y = line & 511, w = img % 3;
    const float2* P = d_expP + (((size_t)layer * NWL + w) * HH + y) * HH;
    size_t base = (size_t)line * HH;
    float2* pl = sm + li * LPLANE;
    float2 v[32];
#pragma unroll
    for (int r = 0; r < 32; r++) v[r] = f[base + 16 * r + t];
    ginv(v, pl, t);
#pragma unroll
    for (int a = 0; a < 32; a++) v[a] = cmulf(v[a], P[16 * a + t]);
    gfwd(v, pl, t);
#pragma unroll
    for (int r = 0; r < 32; r++) f[base + 16 * r + t] = v[r];
}

__global__ void __launch_bounds__(256, 2) k_last(float2* __restrict__ f) {
    extern __shared__ float2 sm[];
    int t = threadIdx.x & 15, li = threadIdx.x >> 4;
    int bi = (int)gridDim.x - 1 - (int)blockIdx.x;      // serpentine (final pass reversed)
    int line = bi * 16 + li;
    size_t base = (size_t)line * HH;
    float2* pl = sm + li * LPLANE;
    float2 v[32];
#pragma unroll
    for (int r = 0; r < 32; r++) v[r] = f[base + 16 * r + t];
    ginv(v, pl, t);
    const float S = 1.0f / 512.0f;
#pragma unroll
    for (int a = 0; a < 32; a++)
        f[base + 16 * a + t] = make_float2(v[a].x * S, v[a].y * S);
}

// ---------------- column pass: 16 cols/block, 16 threads/col, cp.async staging ----------------

__global__ void __launch_bounds__(256, 2) k_col(float2* __restrict__ f, int det, int rev) {
    extern __shared__ float2 T[];
    int bi = rev ? ((int)gridDim.x - 1 - (int)blockIdx.x) : (int)blockIdx.x;
    int img = bi >> 5;
    int c0 = (bi & 31) << 4;
    int w = img % 3;
    float2* base = f + (size_t)img * (HH * HH);

    int colL = threadIdx.x & 15, rowq = threadIdx.x >> 4;
#pragma unroll 8
    for (int it = 0; it < 32; it++) {
        int r = it * 16 + rowq;
        cpasync8(&T[colL * CPLANE + r], &base[(size_t)r * HH + c0 + colL]);
    }
    cpcommit();
    cpwait0();
    __syncthreads();

    int g = threadIdx.x >> 4, t = threadIdx.x & 15;
    float2* pl = T + g * CPLANE;
    float2 v[32];
#pragma unroll
    for (int a = 0; a < 32; a++) v[a] = pl[16 * a + t];
    gfwd(v, pl, t);
    const float2* Hc = (det ? d_HD : d_HL) + ((size_t)w * HH + (c0 + g)) * HH;
#pragma unroll
    for (int r = 0; r < 32; r++) v[r] = cmulf(v[r], Hc[16 * r + t]);
    ginv(v, pl, t);
    __syncwarp();
#pragma unroll
    for (int a = 0; a < 32; a++) pl[16 * a + t] = v[a];
    __syncthreads();

#pragma unroll 8
    for (int it = 0; it < 32; it++) {
        int r = it * 16 + rowq;
        base[(size_t)r * HH + c0 + colL] = T[colL * CPLANE + r];
    }
}

// ---------------- launch ----------------
// Serpentine: pass p traversal alternates; col passes (odd p) reversed, HD col fwd, k_last rev.
extern "C" void kernel_launch(void* const* d_in, const int* in_sizes, int n_in,
                              void* d_out, int out_size) {
    const float* xr = (const float*)d_in[0];
    const float* xi = (const float*)d_in[1];
    const float* pm = (const float*)d_in[2];
    float2* f = (float2*)d_out;

    const int ROWSMEM = 16 * LPLANE * (int)sizeof(float2);   // 67,584 B
    const int COLSMEM = 16 * CPLANE * (int)sizeof(float2);   // 67,712 B
    cudaFuncSetAttribute(k_first,  cudaFuncAttributeMaxDynamicSharedMemorySize, ROWSMEM);
    cudaFuncSetAttribute(k_rowmid, cudaFuncAttributeMaxDynamicSharedMemorySize, ROWSMEM);
    cudaFuncSetAttribute(k_last,   cudaFuncAttributeMaxDynamicSharedMemorySize, ROWSMEM);
    cudaFuncSetAttribute(k_col,    cudaFuncAttributeMaxDynamicSharedMemorySize, COLSMEM);

    k_initH<<<(NWL * HH * HH + 255) / 256, 256>>>();
    k_initP<<<(NLAY * NWL * HH * HH + 255) / 256, 256>>>(pm);

    const int ROWBLKS = NIMG * HH / 16;        // 2304
    const int COLBLKS = NIMG * (HH / 16);      // 2304

    k_first<<<ROWBLKS, 256, ROWSMEM>>>(xr, xi, f);
    for (int l = 0; l < NLAY; l++) {
        k_col<<<COLBLKS, 256, COLSMEM>>>(f, 0, 1);          // reversed
        if (l < NLAY - 1) k_rowmid<<<ROWBLKS, 256, ROWSMEM>>>(f, l + 1);  // forward
    }
    k_col<<<COLBLKS, 256, COLSMEM>>>(f, 1, 0);              // HD pass forward
    k_last<<<ROWBLKS, 256, ROWSMEM>>>(f);                   // reversed
}